// round 12
// baseline (speedup 1.0000x reference)
#include <cuda_runtime.h>
#include <math.h>

#define BB  2
#define VV  5000
#define FF  10000
#define HH  256
#define WW  256
#define TW  1024
#define NB  1024

// fixed key-bin range (keys = max vertex invz, z in [2,4] -> [0.25,0.5] + pad)
#define KMINF 0.2f
#define KMAXF 0.601f
#define INVW  ((float)NB / (KMAXF - KMINF))
#define BINW  ((KMAXF - KMINF) / (float)NB * 1.001f + 1e-6f)
#define BWBIN ((KMAXF - KMINF) / (float)NB)

// Output layout (floats), in reference-return order
#define OFF_IMG    0
#define OFF_DEPTH  393216
#define OFF_VPIX   524288
#define OFF_VTIMG  554288
#define OFF_INDEX  816432
#define OFF_BARY   947504
#define OFF_MASK   1340720

// ---------------- static scratch (no cudaMalloc allowed) -------------------
// face record (R5-proven math): F0=(bx,by,sd0x,sd0y) F1=(cx,cy,sd1x,sd1y)
//                               F2=(ax,ay,sd2x,sd2y) F3=(scc0,scc1,scc2,izdy)
// cull records: BK=(key, packed u8 tile ranges); IZ=(A,B,C,pad) affine invz bound
__device__ float4 g_uF0[BB*FF], g_uF1[BB*FF], g_uF2[BB*FF], g_uF3[BB*FF];
__device__ float2 g_uBK[BB*FF];
__device__ float4 g_uIZ[BB*FF];
__device__ float4 g_sF0[BB*FF], g_sF1[BB*FF], g_sF2[BB*FF], g_sF3[BB*FF];
__device__ float2 g_sBK[BB*FF];
__device__ float4 g_sIZ[BB*FF];
__device__ int    g_sFid[BB*FF];
__device__ int    g_hist[BB*NB], g_cur[BB*NB];   // zeroed by k_raster tail each call

// ---------------------------------------------------------------------------
__device__ __forceinline__ void xform(const float* __restrict__ v,
                                      const float* __restrict__ R,
                                      const float* __restrict__ Kk,
                                      float& ox, float& oy, float& oz)
{
    float x = v[0], y = v[1], z = v[2];
    float cx = R[0]*x + R[1]*y + R[2]*z  + R[3];
    float cy = R[4]*x + R[5]*y + R[6]*z  + R[7];
    float cz = R[8]*x + R[9]*y + R[10]*z + R[11];
    float px = Kk[0]*cx + Kk[1]*cy + Kk[2]*cz;
    float py = Kk[3]*cx + Kk[4]*cy + Kk[5]*cz;
    ox = px / cz; oy = py / cz; oz = cz;
}

__device__ __forceinline__ int fixed_bin(float key)
{
    float kcl = fminf(fmaxf(key, KMINF), KMAXF);
    int bin = (int)((KMAXF - kcl) * INVW);
    return min(NB-1, max(0, bin));
}

// ---------------------------------------------------------------------------
// k_pre: transform (vertex role) + face prep with inline transform + histogram
// ---------------------------------------------------------------------------
__global__ void k_pre(const float* __restrict__ verts,
                      const float* __restrict__ Km,
                      const float* __restrict__ Rt,
                      const int*   __restrict__ vi,
                      float* __restrict__ vpix)
{
    int t = blockIdx.x * blockDim.x + threadIdx.x;

    if (t < BB * VV) {                       // vertex role: write v_pix output
        int b = t / VV;
        float ox, oy, oz;
        xform(verts + t*3, Rt + b*12, Km + b*9, ox, oy, oz);
        vpix[t*3+0] = ox; vpix[t*3+1] = oy; vpix[t*3+2] = oz;
    }

    if (t < BB * FF) {                       // face role: prep + histogram
        int b = t / FF, f = t - b * FF;
        const float* R  = Rt + b*12;
        const float* Kk = Km + b*9;
        int i0 = vi[f*3+0], i1 = vi[f*3+1], i2 = vi[f*3+2];
        float ax, ay, az, bx, by, bz, cx, cy, cz;
        xform(verts + (b*VV + i0)*3, R, Kk, ax, ay, az);
        xform(verts + (b*VV + i1)*3, R, Kk, bx, by, bz);
        xform(verts + (b*VV + i2)*3, R, Kk, cx, cy, cz);

        float area = (bx-ax)*(cy-ay) - (by-ay)*(cx-ax);
        bool ok = (fabsf(area) > 1e-8f) && (az > 0.f) && (bz > 0.f) && (cz > 0.f);

        float key = -1.0f;
        unsigned bbits = 255u;               // lox=255, hix=0 -> always culled
        float4 F0 = make_float4(0,0,0,0), F1 = F0, F2 = F0, F3 = F0;
        float4 IZ = make_float4(0,0,0,0);
        if (ok) {
            float s  = (area > 0.f) ? 1.f : -1.f;
            float ia = 1.0f / area;
            float cc0 = ia / az, cc1 = ia / bz, cc2 = ia / cz;
            float sd0x = s*(cx-bx), sd0y = s*(cy-by);
            float sd1x = s*(ax-cx), sd1y = s*(ay-cy);
            float sd2x = s*(bx-ax), sd2y = s*(by-ay);
            float scc0 = s*cc0, scc1 = s*cc1, scc2 = s*cc2;
            float izdy = sd0x*scc0 + sd1x*scc1 + sd2x*scc2;
            F0 = make_float4(bx, by, sd0x, sd0y);
            F1 = make_float4(cx, cy, sd1x, sd1y);
            F2 = make_float4(ax, ay, sd2x, sd2y);
            F3 = make_float4(scc0, scc1, scc2, izdy);

            float mnx = fminf(ax, fminf(bx, cx)), mxx = fmaxf(ax, fmaxf(bx, cx));
            float mny = fminf(ay, fminf(by, cy)), mxy = fmaxf(ay, fmaxf(by, cy));
            float dd = (mxx - mnx) + (mxy - mny);
            float noise = 2.5e-7f * dd * dd * (fabsf(scc0)+fabsf(scc1)+fabsf(scc2));
            noise = fminf(noise, 10.f);
            key = fmaxf(1.0f/az, fmaxf(1.0f/bz, 1.0f/cz)) * 1.0001f + 1e-4f + noise;

            int lox = min(max((int)floorf((mnx - 0.5f) * 0.0625f),  0), 15);
            int hix = min(max((int)floorf((mxx - 0.5f) * 0.0625f), -1), 15) + 1;
            int loy = min(max((int)floorf((mny - 0.5f) * 0.0625f),  0), 15);
            int hiy = min(max((int)floorf((mxy - 0.5f) * 0.0625f), -1), 15) + 1;
            bbits = (unsigned)lox | ((unsigned)hix << 8)
                  | ((unsigned)loy << 16) | ((unsigned)hiy << 24);

            // affine invz bound: iz(p) = A*px + B*py + C  (CULL ONLY, padded)
            float A = -(sd0y*scc0 + sd1y*scc1 + sd2y*scc2);
            float Bc = izdy;
            float C = (sd0y*bx - sd0x*by)*scc0
                    + (sd1y*cx - sd1x*cy)*scc1
                    + (sd2y*ax - sd2x*ay)*scc2;
            float pad = noise + 1.2e-6f*((fabsf(A) + fabsf(Bc))*300.f + fabsf(C))
                      + 1e-7f;
            IZ = make_float4(A, Bc, C, fminf(pad, 10.f));
        }
        g_uF0[t] = F0; g_uF1[t] = F1; g_uF2[t] = F2; g_uF3[t] = F3;
        g_uBK[t] = make_float2(key, __uint_as_float(bbits));
        g_uIZ[t] = IZ;
        atomicAdd(&g_hist[b*NB + fixed_bin(key)], 1);
    }
}

// ---------------------------------------------------------------------------
// scatter (full records, coalesced sorted output) + per-block inline scan
// ---------------------------------------------------------------------------
__global__ __launch_bounds__(256) void k_scatter()
{
    __shared__ int s_base[BB*NB];
    __shared__ int s_warp[8];
    int tid = threadIdx.x, lane = tid & 31, wid = tid >> 5;

    for (int bb = 0; bb < BB; bb++) {
        int v[4], tsum = 0;
        int bi = bb*NB + tid*4;
#pragma unroll
        for (int k = 0; k < 4; k++) { v[k] = g_hist[bi+k]; tsum += v[k]; }
        int inc = tsum;
#pragma unroll
        for (int o = 1; o < 32; o <<= 1) {
            int y = __shfl_up_sync(0xffffffffu, inc, o);
            if (lane >= o) inc += y;
        }
        if (lane == 31) s_warp[wid] = inc;
        __syncthreads();
        if (wid == 0) {
            int s = (lane < 8) ? s_warp[lane] : 0;
#pragma unroll
            for (int o = 1; o < 8; o <<= 1) {
                int y = __shfl_up_sync(0xffffffffu, s, o);
                if (lane >= o) s += y;
            }
            if (lane < 8) s_warp[lane] = s;
        }
        __syncthreads();
        int pre = ((wid > 0) ? s_warp[wid-1] : 0) + inc - tsum;
#pragma unroll
        for (int k = 0; k < 4; k++) { s_base[bi+k] = pre; pre += v[k]; }
        __syncthreads();
    }

    int t = blockIdx.x * blockDim.x + tid;
    if (t < BB * FF) {
        int b = t / FF, f = t - b * FF;
        float2 bk = g_uBK[t];
        int bin = fixed_bin(bk.x);
        int pos = b*FF + s_base[b*NB + bin] + atomicAdd(&g_cur[b*NB + bin], 1);
        g_sF0[pos] = g_uF0[t];
        g_sF1[pos] = g_uF1[t];
        g_sF2[pos] = g_uF2[t];
        g_sF3[pos] = g_uF3[t];
        g_sBK[pos] = bk;
        g_sIZ[pos] = g_uIZ[t];
        g_sFid[pos] = f;
    }
}

// ---------------------------------------------------------------------------
// shading for one pixel (reference render+interpolate+grid_sample semantics)
// ---------------------------------------------------------------------------
__device__ __forceinline__ void shade_pixel(
    int b, int x, int y, int idx,
    const float* __restrict__ tex, const float* __restrict__ vt,
    const int* __restrict__ vi, const int* __restrict__ vti,
    const float* __restrict__ vpix, float* __restrict__ out)
{
    bool m  = (idx != -1);
    int it  = idx > 0 ? idx : 0;

    int i0 = vi[it*3+0], i1 = vi[it*3+1], i2 = vi[it*3+2];
    const float* pa = vpix + (b*VV + i0) * 3;
    const float* pb = vpix + (b*VV + i1) * 3;
    const float* pc = vpix + (b*VV + i2) * 3;
    float ax = pa[0], ay = pa[1], az = pa[2];
    float bx = pb[0], by = pb[1], bz = pb[2];
    float cx = pc[0], cy = pc[1], cz = pc[2];

    float px = x + 0.5f, py = y + 0.5f;
    float w0 = (cx-bx)*(py-by) - (cy-by)*(px-bx);
    float w1 = (ax-cx)*(py-cy) - (ay-cy)*(px-cx);
    float w2 = (bx-ax)*(py-ay) - (by-ay)*(px-ax);
    float area = w0 + w1 + w2;
    float ar = (fabsf(area) > 1e-8f) ? area : 1.0f;
    float f0 = w0 / ar / fmaxf(az, 1e-8f);
    float f1 = w1 / ar / fmaxf(bz, 1e-8f);
    float f2 = w2 / ar / fmaxf(cz, 1e-8f);
    float invz = f0 + f1 + f2;
    float invz_s = (fabsf(invz) > 1e-12f) ? invz : 1.0f;
    float depth = 1.0f / invz_s;
    float b0 = f0 / invz_s, b1 = f1 / invz_s, b2 = f2 / invz_s;

    float depth_o = m ? depth : 0.f;
    float bb0 = m ? b0 : 0.f;
    float bb1 = m ? b1 : 0.f;
    float bb2 = m ? b2 : 0.f;

    int t0 = vti[it*3+0], t1 = vti[it*3+1], t2 = vti[it*3+2];
    float a0x = vt[t0*2+0]*2.f - 1.f, a0y = vt[t0*2+1]*2.f - 1.f;
    float a1x = vt[t1*2+0]*2.f - 1.f, a1y = vt[t1*2+1]*2.f - 1.f;
    float a2x = vt[t2*2+0]*2.f - 1.f, a2y = vt[t2*2+1]*2.f - 1.f;
    float gxc = a0x*bb0 + a1x*bb1 + a2x*bb2;
    float gyc = a0y*bb0 + a1y*bb1 + a2y*bb2;

    float img0 = 0.f, img1 = 0.f, img2 = 0.f;
    if (m) {
        float sx = (gxc + 1.f) * (TW * 0.5f) - 0.5f;
        float sy = (gyc + 1.f) * (TW * 0.5f) - 0.5f;
        float fx0 = floorf(sx), fy0 = floorf(sy);
        float wx = sx - fx0, wy = sy - fy0;
        int x0 = (int)fx0, y0i = (int)fy0;
        float wgt[4] = { (1.f-wx)*(1.f-wy), wx*(1.f-wy), (1.f-wx)*wy, wx*wy };
        int cxs[4] = { x0, x0+1, x0,   x0+1 };
        int cys[4] = { y0i, y0i, y0i+1, y0i+1 };
        const float* tb = tex + (size_t)b * 3 * TW * TW;
#pragma unroll
        for (int c = 0; c < 4; c++) {
            int ix = cxs[c], iy = cys[c];
            bool val = (ix >= 0) && (ix < TW) && (iy >= 0) && (iy < TW);
            int ixc = min(max(ix, 0), TW-1);
            int iyc = min(max(iy, 0), TW-1);
            float wv = val ? wgt[c] : 0.f;
            size_t o = (size_t)iyc * TW + ixc;
            img0 += tb[0*TW*TW + o] * wv;
            img1 += tb[1*TW*TW + o] * wv;
            img2 += tb[2*TW*TW + o] * wv;
        }
    }

    int p = (b * HH + y) * WW + x;
    out[OFF_IMG   + ((b*3 + 0)*HH + y)*WW + x] = img0;
    out[OFF_IMG   + ((b*3 + 1)*HH + y)*WW + x] = img1;
    out[OFF_IMG   + ((b*3 + 2)*HH + y)*WW + x] = img2;
    out[OFF_DEPTH + p] = depth_o;
    out[OFF_VTIMG + ((b*2 + 0)*HH + y)*WW + x] = gxc;
    out[OFF_VTIMG + ((b*2 + 1)*HH + y)*WW + x] = gyc;
    out[OFF_INDEX + p] = (float)idx;
    out[OFF_BARY  + ((b*3 + 0)*HH + y)*WW + x] = bb0;
    out[OFF_BARY  + ((b*3 + 1)*HH + y)*WW + x] = bb1;
    out[OFF_BARY  + ((b*3 + 2)*HH + y)*WW + x] = bb2;
    out[OFF_MASK  + p] = m ? 1.f : 0.f;
}

// ---------------------------------------------------------------------------
// tile rasterizer: 16x16 tile, 128 thr, 2 px/thread. Low-overhead chunk loop:
// sorted-stream chunk bound (no max-reduction), smem atomicMin tileMin (stale-
// safe), warp-segmented compaction + double buffering (1 sync per chunk).
// Selection math verbatim R5/R8 (bit-proven).
// ---------------------------------------------------------------------------
#define TPB    128
#define TILE   16

__global__ __launch_bounds__(TPB) void k_raster(
    const float* __restrict__ tex, const float* __restrict__ vt,
    const int* __restrict__ vi, const int* __restrict__ vti,
    const float* __restrict__ vpix, float* __restrict__ out)
{
    __shared__ float4 sF0[2][TPB], sF1[2][TPB], sF2[2][TPB], sF3[2][TPB];
    __shared__ int    sFid[2][TPB];
    __shared__ int    s_cnt[2][TPB/32];
    __shared__ int    s_tmin;          // tileMin as int-ordered float (>=0)

    int b   = blockIdx.z;
    int tx  = blockIdx.x, ty = blockIdx.y;
    int tx0 = tx * TILE, ty0 = ty * TILE;
    int tid = threadIdx.x;
    int warp = tid >> 5, lane = tid & 31;
    int lx  = tid & (TILE-1);
    int lyg = tid >> 4;                       // 0..7

    float px  = tx0 + lx + 0.5f;
    float py0 = ty0 + lyg * 2 + 0.5f;
    float txA = tx0 + 0.5f, txB = tx0 + TILE - 0.5f;
    float tyA = ty0 + 0.5f, tyB = ty0 + TILE - 0.5f;

    float biv0 = 0.f, biv1 = 0.f;
    int   bf0 = -1, bf1 = -1;

    if (tid == 0) s_tmin = 0;
    __syncthreads();

    const float4* f0A = g_sF0 + (size_t)b * FF;
    const float4* f1A = g_sF1 + (size_t)b * FF;
    const float4* f2A = g_sF2 + (size_t)b * FF;
    const float4* f3A = g_sF3 + (size_t)b * FF;
    const float2* bkA = g_sBK + (size_t)b * FF;
    const float4* izA = g_sIZ + (size_t)b * FF;
    const int*    fArr= g_sFid+ (size_t)b * FF;

    int buf = 0;
    for (int base = 0; base < FF; base += TPB, buf ^= 1) {
        // sorted-stream bound: all faces from 'base' on have key <= binTop
        float kb = bkA[base].x;                       // uniform broadcast load
        int   bbin = fixed_bin(kb);
        float tileMin = __int_as_float(*(volatile int*)&s_tmin);  // stale-safe
        if (bbin != 0) {
            float bound = KMAXF - (float)bbin * BWBIN + 1e-5f;
            if (bound <= tileMin) break;              // provably nothing left
        }

        int f = base + tid;
        float key = -1.0f; unsigned bbits = 255u;
        if (f < FF) {
            float2 bk = bkA[f];
            key = bk.x; bbits = __float_as_uint(bk.y);
        }

        // cull: depth-useless, tile-bbox miss, or tile-local invz bound too far
        bool keep = (key > tileMin);
        if (keep) {
            int lox = bbits & 255, hix = (bbits >> 8) & 255;
            int loy = (bbits >> 16) & 255, hiy = bbits >> 24;
            keep = (tx >= lox) && (tx < hix) && (ty >= loy) && (ty < hiy);
        }
        if (keep) {
            float4 iz = izA[f];
            float tmax = fmaxf(iz.x*txA, iz.x*txB)
                       + fmaxf(iz.y*tyA, iz.y*tyB) + iz.z + iz.w;
            keep = tmax > tileMin;
        }

        // warp-segmented compaction into double-buffered smem
        unsigned bal = __ballot_sync(0xffffffffu, keep);
        if (lane == 0) s_cnt[buf][warp] = __popc(bal);
        if (keep) {
            int pos = warp*32 + __popc(bal & ((1u << lane) - 1u));
            sF0[buf][pos] = f0A[f]; sF1[buf][pos] = f1A[f];
            sF2[buf][pos] = f2A[f]; sF3[buf][pos] = f3A[f];
            sFid[buf][pos] = fArr[f];
        }
        __syncthreads();      // counts + faces visible; prev buf done last iter

#pragma unroll
        for (int w = 0; w < TPB/32; w++) {
            int cw = s_cnt[buf][w];
            for (int j = 0; j < cw; j++) {
                int idx = w*32 + j;
                float4 q0 = sF0[buf][idx], q1 = sF1[buf][idx];
                float4 q2 = sF2[buf][idx], q3 = sF3[buf][idx];
                float W0 = q0.z * (py0 - q0.y) - q0.w * (px - q0.x);
                float W1 = q1.z * (py0 - q1.y) - q1.w * (px - q1.x);
                float W2 = q2.z * (py0 - q2.y) - q2.w * (px - q2.x);
                float iz = W0 * q3.x + W1 * q3.y + W2 * q3.z;
                float tm = fminf(W0, fminf(W1, W2));
                if (tm >= 0.f && iz > biv0) { biv0 = iz; bf0 = sFid[buf][idx]; }
                float W0b = W0 + q0.z, W1b = W1 + q1.z, W2b = W2 + q2.z;
                float izb = iz + q3.w;
                float tmb = fminf(W0b, fminf(W1b, W2b));
                if (tmb >= 0.f && izb > biv1) { biv1 = izb; bf1 = sFid[buf][idx]; }
            }
        }

        // lazily publish this thread's best (monotone; stale reads are safe)
        atomicMin(&s_tmin, __float_as_int(fminf(biv0, biv1)));
    }

    // re-zero sort state for the next graph replay (first call: zero-init globals)
    {
        int gb = (blockIdx.z * gridDim.y + blockIdx.y) * gridDim.x + blockIdx.x;
        int gt = gb * TPB + tid;
        if (gt < BB*NB) { g_hist[gt] = 0; g_cur[gt] = 0; }
    }

    // fused shading of this thread's 2 pixels
    int y0 = ty0 + lyg * 2;
    int x  = tx0 + lx;
    shade_pixel(b, x, y0,     bf0, tex, vt, vi, vti, vpix, out);
    shade_pixel(b, x, y0 + 1, bf1, tex, vt, vi, vti, vpix, out);
}

// ---------------------------------------------------------------------------
extern "C" void kernel_launch(void* const* d_in, const int* in_sizes, int n_in,
                              void* d_out, int out_size)
{
    const float* verts = (const float*)d_in[0];
    const float* tex   = (const float*)d_in[1];
    const float* Km    = (const float*)d_in[2];
    const float* Rt    = (const float*)d_in[3];
    const float* vt    = (const float*)d_in[4];
    const int*   vi    = (const int*)  d_in[5];
    const int*   vti   = (const int*)  d_in[6];
    float* out = (float*)d_out;

    float* vpix = out + OFF_VPIX;   // v_pix output doubles as scratch

    k_pre    <<<(BB*FF + 255)/256, 256>>>(verts, Km, Rt, vi, vpix);
    k_scatter<<<(BB*FF + 255)/256, 256>>>();
    dim3 rg(WW / TILE, HH / TILE, BB);
    k_raster <<<rg, TPB>>>(tex, vt, vi, vti, vpix, out);
}

// round 14
// speedup vs baseline: 6.8020x; 6.8020x over previous
#include <cuda_runtime.h>
#include <math.h>

#define BB  2
#define VV  5000
#define FF  10000
#define HH  256
#define WW  256
#define TW  1024
#define NB  1024

// fixed key-bin range (keys = max vertex invz, z in [2,4] -> [0.25,0.5] + pad)
#define KMINF 0.2f
#define KMAXF 0.601f
#define INVW  ((float)NB / (KMAXF - KMINF))
#define BWBIN ((KMAXF - KMINF) / (float)NB)

// Output layout (floats), in reference-return order
#define OFF_IMG    0
#define OFF_DEPTH  393216
#define OFF_VPIX   524288
#define OFF_VTIMG  554288
#define OFF_INDEX  816432
#define OFF_BARY   947504
#define OFF_MASK   1340720

// ---------------- static scratch (no cudaMalloc allowed) -------------------
// face record (R5-proven math): F0=(bx,by,sd0x,sd0y) F1=(cx,cy,sd1x,sd1y)
//                               F2=(ax,ay,sd2x,sd2y) F3=(scc0,scc1,scc2,izdy)
// cull records: BK=(key, packed u8 tile ranges); IZ=(A,B,C,pad) affine invz bound
__device__ float4 g_uF0[BB*FF], g_uF1[BB*FF], g_uF2[BB*FF], g_uF3[BB*FF];
__device__ float2 g_uBK[BB*FF];
__device__ float4 g_uIZ[BB*FF];
__device__ float4 g_sF0[BB*FF], g_sF1[BB*FF], g_sF2[BB*FF], g_sF3[BB*FF];
__device__ float2 g_sBK[BB*FF];
__device__ float4 g_sIZ[BB*FF];
__device__ int    g_sFid[BB*FF];
__device__ int    g_hist[BB*NB], g_cur[BB*NB];   // zeroed by k_raster tail each call

// ---------------------------------------------------------------------------
__device__ __forceinline__ void xform(const float* __restrict__ v,
                                      const float* __restrict__ R,
                                      const float* __restrict__ Kk,
                                      float& ox, float& oy, float& oz)
{
    float x = v[0], y = v[1], z = v[2];
    float cx = R[0]*x + R[1]*y + R[2]*z  + R[3];
    float cy = R[4]*x + R[5]*y + R[6]*z  + R[7];
    float cz = R[8]*x + R[9]*y + R[10]*z + R[11];
    float px = Kk[0]*cx + Kk[1]*cy + Kk[2]*cz;
    float py = Kk[3]*cx + Kk[4]*cy + Kk[5]*cz;
    ox = px / cz; oy = py / cz; oz = cz;
}

__device__ __forceinline__ int fixed_bin(float key)
{
    float kcl = fminf(fmaxf(key, KMINF), KMAXF);
    int bin = (int)((KMAXF - kcl) * INVW);
    return min(NB-1, max(0, bin));
}

// ---------------------------------------------------------------------------
// k_pre: transform (vertex role) + face prep with inline transform + histogram
// ---------------------------------------------------------------------------
__global__ void k_pre(const float* __restrict__ verts,
                      const float* __restrict__ Km,
                      const float* __restrict__ Rt,
                      const int*   __restrict__ vi,
                      float* __restrict__ vpix)
{
    int t = blockIdx.x * blockDim.x + threadIdx.x;

    if (t < BB * VV) {                       // vertex role: write v_pix output
        int b = t / VV;
        float ox, oy, oz;
        xform(verts + t*3, Rt + b*12, Km + b*9, ox, oy, oz);
        vpix[t*3+0] = ox; vpix[t*3+1] = oy; vpix[t*3+2] = oz;
    }

    if (t < BB * FF) {                       // face role: prep + histogram
        int b = t / FF, f = t - b * FF;
        const float* R  = Rt + b*12;
        const float* Kk = Km + b*9;
        int i0 = vi[f*3+0], i1 = vi[f*3+1], i2 = vi[f*3+2];
        float ax, ay, az, bx, by, bz, cx, cy, cz;
        xform(verts + (b*VV + i0)*3, R, Kk, ax, ay, az);
        xform(verts + (b*VV + i1)*3, R, Kk, bx, by, bz);
        xform(verts + (b*VV + i2)*3, R, Kk, cx, cy, cz);

        float area = (bx-ax)*(cy-ay) - (by-ay)*(cx-ax);
        bool ok = (fabsf(area) > 1e-8f) && (az > 0.f) && (bz > 0.f) && (cz > 0.f);

        float key = -1.0f;
        unsigned bbits = 255u;               // lox=255, hix=0 -> always culled
        float4 F0 = make_float4(0,0,0,0), F1 = F0, F2 = F0, F3 = F0;
        float4 IZ = make_float4(0,0,0,0);
        if (ok) {
            float s  = (area > 0.f) ? 1.f : -1.f;
            float ia = 1.0f / area;
            float cc0 = ia / az, cc1 = ia / bz, cc2 = ia / cz;
            float sd0x = s*(cx-bx), sd0y = s*(cy-by);
            float sd1x = s*(ax-cx), sd1y = s*(ay-cy);
            float sd2x = s*(bx-ax), sd2y = s*(by-ay);
            float scc0 = s*cc0, scc1 = s*cc1, scc2 = s*cc2;
            float izdy = sd0x*scc0 + sd1x*scc1 + sd2x*scc2;
            F0 = make_float4(bx, by, sd0x, sd0y);
            F1 = make_float4(cx, cy, sd1x, sd1y);
            F2 = make_float4(ax, ay, sd2x, sd2y);
            F3 = make_float4(scc0, scc1, scc2, izdy);

            float mnx = fminf(ax, fminf(bx, cx)), mxx = fmaxf(ax, fmaxf(bx, cx));
            float mny = fminf(ay, fminf(by, cy)), mxy = fmaxf(ay, fmaxf(by, cy));
            float dd = (mxx - mnx) + (mxy - mny);
            float noise = 2.5e-7f * dd * dd * (fabsf(scc0)+fabsf(scc1)+fabsf(scc2));
            noise = fminf(noise, 10.f);
            key = fmaxf(1.0f/az, fmaxf(1.0f/bz, 1.0f/cz)) * 1.0001f + 1e-4f + noise;

            int lox = min(max((int)floorf((mnx - 0.5f) * 0.0625f),  0), 15);
            int hix = min(max((int)floorf((mxx - 0.5f) * 0.0625f), -1), 15) + 1;
            int loy = min(max((int)floorf((mny - 0.5f) * 0.0625f),  0), 15);
            int hiy = min(max((int)floorf((mxy - 0.5f) * 0.0625f), -1), 15) + 1;
            bbits = (unsigned)lox | ((unsigned)hix << 8)
                  | ((unsigned)loy << 16) | ((unsigned)hiy << 24);

            // affine invz bound: iz(p) = A*px + B*py + C  (CULL ONLY, padded)
            float A = -(sd0y*scc0 + sd1y*scc1 + sd2y*scc2);
            float Bc = izdy;
            float C = (sd0y*bx - sd0x*by)*scc0
                    + (sd1y*cx - sd1x*cy)*scc1
                    + (sd2y*ax - sd2x*ay)*scc2;
            float pad = noise + 1.2e-6f*((fabsf(A) + fabsf(Bc))*300.f + fabsf(C))
                      + 1e-7f;
            IZ = make_float4(A, Bc, C, fminf(pad, 10.f));
        }
        g_uF0[t] = F0; g_uF1[t] = F1; g_uF2[t] = F2; g_uF3[t] = F3;
        g_uBK[t] = make_float2(key, __uint_as_float(bbits));
        g_uIZ[t] = IZ;
        atomicAdd(&g_hist[b*NB + fixed_bin(key)], 1);
    }
}

// ---------------------------------------------------------------------------
// scatter (full records, coalesced sorted output) + per-block inline scan
// ---------------------------------------------------------------------------
__global__ __launch_bounds__(256) void k_scatter()
{
    __shared__ int s_base[BB*NB];
    __shared__ int s_warp[8];
    int tid = threadIdx.x, lane = tid & 31, wid = tid >> 5;

    for (int bb = 0; bb < BB; bb++) {
        int v[4], tsum = 0;
        int bi = bb*NB + tid*4;
#pragma unroll
        for (int k = 0; k < 4; k++) { v[k] = g_hist[bi+k]; tsum += v[k]; }
        int inc = tsum;
#pragma unroll
        for (int o = 1; o < 32; o <<= 1) {
            int y = __shfl_up_sync(0xffffffffu, inc, o);
            if (lane >= o) inc += y;
        }
        if (lane == 31) s_warp[wid] = inc;
        __syncthreads();
        if (wid == 0) {
            int s = (lane < 8) ? s_warp[lane] : 0;
#pragma unroll
            for (int o = 1; o < 8; o <<= 1) {
                int y = __shfl_up_sync(0xffffffffu, s, o);
                if (lane >= o) s += y;
            }
            if (lane < 8) s_warp[lane] = s;
        }
        __syncthreads();
        int pre = ((wid > 0) ? s_warp[wid-1] : 0) + inc - tsum;
#pragma unroll
        for (int k = 0; k < 4; k++) { s_base[bi+k] = pre; pre += v[k]; }
        __syncthreads();
    }

    int t = blockIdx.x * blockDim.x + tid;
    if (t < BB * FF) {
        int b = t / FF, f = t - b * FF;
        float2 bk = g_uBK[t];
        int bin = fixed_bin(bk.x);
        int pos = b*FF + s_base[b*NB + bin] + atomicAdd(&g_cur[b*NB + bin], 1);
        g_sF0[pos] = g_uF0[t];
        g_sF1[pos] = g_uF1[t];
        g_sF2[pos] = g_uF2[t];
        g_sF3[pos] = g_uF3[t];
        g_sBK[pos] = bk;
        g_sIZ[pos] = g_uIZ[t];
        g_sFid[pos] = f;
    }
}

// ---------------------------------------------------------------------------
// shading for one pixel (reference render+interpolate+grid_sample semantics)
// ---------------------------------------------------------------------------
__device__ __forceinline__ void shade_pixel(
    int b, int x, int y, int idx,
    const float* __restrict__ tex, const float* __restrict__ vt,
    const int* __restrict__ vi, const int* __restrict__ vti,
    const float* __restrict__ vpix, float* __restrict__ out)
{
    bool m  = (idx != -1);
    int it  = idx > 0 ? idx : 0;

    int i0 = vi[it*3+0], i1 = vi[it*3+1], i2 = vi[it*3+2];
    const float* pa = vpix + (b*VV + i0) * 3;
    const float* pb = vpix + (b*VV + i1) * 3;
    const float* pc = vpix + (b*VV + i2) * 3;
    float ax = pa[0], ay = pa[1], az = pa[2];
    float bx = pb[0], by = pb[1], bz = pb[2];
    float cx = pc[0], cy = pc[1], cz = pc[2];

    float px = x + 0.5f, py = y + 0.5f;
    float w0 = (cx-bx)*(py-by) - (cy-by)*(px-bx);
    float w1 = (ax-cx)*(py-cy) - (ay-cy)*(px-cx);
    float w2 = (bx-ax)*(py-ay) - (by-ay)*(px-ax);
    float area = w0 + w1 + w2;
    float ar = (fabsf(area) > 1e-8f) ? area : 1.0f;
    float f0 = w0 / ar / fmaxf(az, 1e-8f);
    float f1 = w1 / ar / fmaxf(bz, 1e-8f);
    float f2 = w2 / ar / fmaxf(cz, 1e-8f);
    float invz = f0 + f1 + f2;
    float invz_s = (fabsf(invz) > 1e-12f) ? invz : 1.0f;
    float depth = 1.0f / invz_s;
    float b0 = f0 / invz_s, b1 = f1 / invz_s, b2 = f2 / invz_s;

    float depth_o = m ? depth : 0.f;
    float bb0 = m ? b0 : 0.f;
    float bb1 = m ? b1 : 0.f;
    float bb2 = m ? b2 : 0.f;

    int t0 = vti[it*3+0], t1 = vti[it*3+1], t2 = vti[it*3+2];
    float a0x = vt[t0*2+0]*2.f - 1.f, a0y = vt[t0*2+1]*2.f - 1.f;
    float a1x = vt[t1*2+0]*2.f - 1.f, a1y = vt[t1*2+1]*2.f - 1.f;
    float a2x = vt[t2*2+0]*2.f - 1.f, a2y = vt[t2*2+1]*2.f - 1.f;
    float gxc = a0x*bb0 + a1x*bb1 + a2x*bb2;
    float gyc = a0y*bb0 + a1y*bb1 + a2y*bb2;

    float img0 = 0.f, img1 = 0.f, img2 = 0.f;
    if (m) {
        float sx = (gxc + 1.f) * (TW * 0.5f) - 0.5f;
        float sy = (gyc + 1.f) * (TW * 0.5f) - 0.5f;
        float fx0 = floorf(sx), fy0 = floorf(sy);
        float wx = sx - fx0, wy = sy - fy0;
        int x0 = (int)fx0, y0i = (int)fy0;
        float wgt[4] = { (1.f-wx)*(1.f-wy), wx*(1.f-wy), (1.f-wx)*wy, wx*wy };
        int cxs[4] = { x0, x0+1, x0,   x0+1 };
        int cys[4] = { y0i, y0i, y0i+1, y0i+1 };
        const float* tb = tex + (size_t)b * 3 * TW * TW;
#pragma unroll
        for (int c = 0; c < 4; c++) {
            int ix = cxs[c], iy = cys[c];
            bool val = (ix >= 0) && (ix < TW) && (iy >= 0) && (iy < TW);
            int ixc = min(max(ix, 0), TW-1);
            int iyc = min(max(iy, 0), TW-1);
            float wv = val ? wgt[c] : 0.f;
            size_t o = (size_t)iyc * TW + ixc;
            img0 += tb[0*TW*TW + o] * wv;
            img1 += tb[1*TW*TW + o] * wv;
            img2 += tb[2*TW*TW + o] * wv;
        }
    }

    int p = (b * HH + y) * WW + x;
    out[OFF_IMG   + ((b*3 + 0)*HH + y)*WW + x] = img0;
    out[OFF_IMG   + ((b*3 + 1)*HH + y)*WW + x] = img1;
    out[OFF_IMG   + ((b*3 + 2)*HH + y)*WW + x] = img2;
    out[OFF_DEPTH + p] = depth_o;
    out[OFF_VTIMG + ((b*2 + 0)*HH + y)*WW + x] = gxc;
    out[OFF_VTIMG + ((b*2 + 1)*HH + y)*WW + x] = gyc;
    out[OFF_INDEX + p] = (float)idx;
    out[OFF_BARY  + ((b*3 + 0)*HH + y)*WW + x] = bb0;
    out[OFF_BARY  + ((b*3 + 1)*HH + y)*WW + x] = bb1;
    out[OFF_BARY  + ((b*3 + 2)*HH + y)*WW + x] = bb2;
    out[OFF_MASK  + p] = m ? 1.f : 0.f;
}

// ---------------------------------------------------------------------------
// tile rasterizer: 16x16 tile, 128 thr, 2 px/thread. Per chunk: fresh shfl
// min-reduction for tileMin (race-free), sorted-stream bound for the break
// (no max-reduction), warp-segmented compaction, 2 syncs. Selection math
// verbatim R5/R8 (bit-proven).
// ---------------------------------------------------------------------------
#define TPB    128
#define TILE   16

__global__ __launch_bounds__(TPB) void k_raster(
    const float* __restrict__ tex, const float* __restrict__ vt,
    const int* __restrict__ vi, const int* __restrict__ vti,
    const float* __restrict__ vpix, float* __restrict__ out)
{
    __shared__ float4 sF0[TPB], sF1[TPB], sF2[TPB], sF3[TPB];
    __shared__ int    sFid[TPB];
    __shared__ int    s_cnt[TPB/32];
    __shared__ float  s_min[TPB/32];

    int b   = blockIdx.z;
    int tx  = blockIdx.x, ty = blockIdx.y;
    int tx0 = tx * TILE, ty0 = ty * TILE;
    int tid = threadIdx.x;
    int warp = tid >> 5, lane = tid & 31;
    int lx  = tid & (TILE-1);
    int lyg = tid >> 4;                       // 0..7

    float px  = tx0 + lx + 0.5f;
    float py0 = ty0 + lyg * 2 + 0.5f;
    float txA = tx0 + 0.5f, txB = tx0 + TILE - 0.5f;
    float tyA = ty0 + 0.5f, tyB = ty0 + TILE - 0.5f;

    float biv0 = 0.f, biv1 = 0.f;
    int   bf0 = -1, bf1 = -1;

    const float4* f0A = g_sF0 + (size_t)b * FF;
    const float4* f1A = g_sF1 + (size_t)b * FF;
    const float4* f2A = g_sF2 + (size_t)b * FF;
    const float4* f3A = g_sF3 + (size_t)b * FF;
    const float2* bkA = g_sBK + (size_t)b * FF;
    const float4* izA = g_sIZ + (size_t)b * FF;
    const int*    fArr= g_sFid+ (size_t)b * FF;

    for (int base = 0; base < FF; base += TPB) {
        // 1) fresh tileMin: warp butterfly + cross-warp via smem
        float wmin = fminf(biv0, biv1);
#pragma unroll
        for (int o = 16; o; o >>= 1)
            wmin = fminf(wmin, __shfl_xor_sync(0xffffffffu, wmin, o));
        if (lane == 0) s_min[warp] = wmin;
        __syncthreads();                                   // sync #1
        float tileMin = fminf(fminf(s_min[0], s_min[1]),
                              fminf(s_min[2], s_min[3]));

        // 2) sorted-stream break: all keys from base on <= binTop(bin(key[base]))
        float kb = bkA[base].x;
        int   bbin = fixed_bin(kb);
        if (bbin != 0) {
            float bound = KMAXF - (float)bbin * BWBIN + 1e-5f;
            if (bound <= tileMin) break;   // provably nothing left can win
        }

        // 3) load + cull (depth-useless, tile-bbox miss, affine invz bound)
        int f = base + tid;
        float key = -1.0f; unsigned bbits = 255u;
        if (f < FF) {
            float2 bk = bkA[f];
            key = bk.x; bbits = __float_as_uint(bk.y);
        }
        bool keep = (key > tileMin);
        if (keep) {
            int lox = bbits & 255, hix = (bbits >> 8) & 255;
            int loy = (bbits >> 16) & 255, hiy = bbits >> 24;
            keep = (tx >= lox) && (tx < hix) && (ty >= loy) && (ty < hiy);
        }
        if (keep) {
            float4 iz = izA[f];
            float tmax = fmaxf(iz.x*txA, iz.x*txB)
                       + fmaxf(iz.y*tyA, iz.y*tyB) + iz.z + iz.w;
            keep = tmax > tileMin;
        }

        // warp-segmented compaction (warp w owns slots [32w, 32w+cnt))
        unsigned bal = __ballot_sync(0xffffffffu, keep);
        if (lane == 0) s_cnt[warp] = __popc(bal);
        if (keep) {
            int pos = warp*32 + __popc(bal & ((1u << lane) - 1u));
            sF0[pos] = f0A[f]; sF1[pos] = f1A[f];
            sF2[pos] = f2A[f]; sF3[pos] = f3A[f];
            sFid[pos] = fArr[f];
        }
        __syncthreads();                                   // sync #2

        // 4) inner loop over warp segments
#pragma unroll
        for (int w = 0; w < TPB/32; w++) {
            int cw = s_cnt[w];
            for (int j = 0; j < cw; j++) {
                int idx = w*32 + j;
                float4 q0 = sF0[idx], q1 = sF1[idx];
                float4 q2 = sF2[idx], q3 = sF3[idx];
                float W0 = q0.z * (py0 - q0.y) - q0.w * (px - q0.x);
                float W1 = q1.z * (py0 - q1.y) - q1.w * (px - q1.x);
                float W2 = q2.z * (py0 - q2.y) - q2.w * (px - q2.x);
                float iz = W0 * q3.x + W1 * q3.y + W2 * q3.z;
                float tm = fminf(W0, fminf(W1, W2));
                if (tm >= 0.f && iz > biv0) { biv0 = iz; bf0 = sFid[idx]; }
                float W0b = W0 + q0.z, W1b = W1 + q1.z, W2b = W2 + q2.z;
                float izb = iz + q3.w;
                float tmb = fminf(W0b, fminf(W1b, W2b));
                if (tmb >= 0.f && izb > biv1) { biv1 = izb; bf1 = sFid[idx]; }
            }
        }
    }

    // re-zero sort state for the next graph replay (first call: zero-init globals)
    {
        int gb = (blockIdx.z * gridDim.y + blockIdx.y) * gridDim.x + blockIdx.x;
        int gt = gb * TPB + tid;
        if (gt < BB*NB) { g_hist[gt] = 0; g_cur[gt] = 0; }
    }

    // fused shading of this thread's 2 pixels
    int y0 = ty0 + lyg * 2;
    int x  = tx0 + lx;
    shade_pixel(b, x, y0,     bf0, tex, vt, vi, vti, vpix, out);
    shade_pixel(b, x, y0 + 1, bf1, tex, vt, vi, vti, vpix, out);
}

// ---------------------------------------------------------------------------
extern "C" void kernel_launch(void* const* d_in, const int* in_sizes, int n_in,
                              void* d_out, int out_size)
{
    const float* verts = (const float*)d_in[0];
    const float* tex   = (const float*)d_in[1];
    const float* Km    = (const float*)d_in[2];
    const float* Rt    = (const float*)d_in[3];
    const float* vt    = (const float*)d_in[4];
    const int*   vi    = (const int*)  d_in[5];
    const int*   vti   = (const int*)  d_in[6];
    float* out = (float*)d_out;

    float* vpix = out + OFF_VPIX;   // v_pix output doubles as scratch

    k_pre    <<<(BB*FF + 255)/256, 256>>>(verts, Km, Rt, vi, vpix);
    k_scatter<<<(BB*FF + 255)/256, 256>>>();
    dim3 rg(WW / TILE, HH / TILE, BB);
    k_raster <<<rg, TPB>>>(tex, vt, vi, vti, vpix, out);
}

// round 15
// speedup vs baseline: 7.5285x; 1.1068x over previous
#include <cuda_runtime.h>
#include <math.h>

#define BB  2
#define VV  5000
#define FF  10000
#define HH  256
#define WW  256
#define TW  1024
#define NB  1024

// fixed key-bin range (keys = max vertex invz, z in [2,4] -> [0.25,0.5] + pad)
#define KMINF 0.2f
#define KMAXF 0.601f
#define INVW  ((float)NB / (KMAXF - KMINF))
#define BWBIN ((KMAXF - KMINF) / (float)NB)

// Output layout (floats), in reference-return order
#define OFF_IMG    0
#define OFF_DEPTH  393216
#define OFF_VPIX   524288
#define OFF_VTIMG  554288
#define OFF_INDEX  816432
#define OFF_BARY   947504
#define OFF_MASK   1340720

// ---------------- static scratch (no cudaMalloc allowed) -------------------
// face record (R5-proven math): F0=(bx,by,sd0x,sd0y) F1=(cx,cy,sd1x,sd1y)
//                               F2=(ax,ay,sd2x,sd2y) F3=(scc0,scc1,scc2,izdy)
// cull records: BK=(key, packed u8 tile ranges); IZ=(A,B,C,pad) affine invz bound
__device__ float4 g_uF0[BB*FF], g_uF1[BB*FF], g_uF2[BB*FF], g_uF3[BB*FF];
__device__ float2 g_uBK[BB*FF];
__device__ float4 g_uIZ[BB*FF];
__device__ float4 g_sF0[BB*FF], g_sF1[BB*FF], g_sF2[BB*FF], g_sF3[BB*FF];
__device__ float2 g_sBK[BB*FF];
__device__ float4 g_sIZ[BB*FF];
__device__ int    g_sFid[BB*FF];
__device__ int    g_hist[BB*NB], g_cur[BB*NB];   // zeroed by k_raster tail each call

// ---------------------------------------------------------------------------
__device__ __forceinline__ void xform(const float* __restrict__ v,
                                      const float* __restrict__ R,
                                      const float* __restrict__ Kk,
                                      float& ox, float& oy, float& oz)
{
    float x = v[0], y = v[1], z = v[2];
    float cx = R[0]*x + R[1]*y + R[2]*z  + R[3];
    float cy = R[4]*x + R[5]*y + R[6]*z  + R[7];
    float cz = R[8]*x + R[9]*y + R[10]*z + R[11];
    float px = Kk[0]*cx + Kk[1]*cy + Kk[2]*cz;
    float py = Kk[3]*cx + Kk[4]*cy + Kk[5]*cz;
    ox = px / cz; oy = py / cz; oz = cz;
}

__device__ __forceinline__ int fixed_bin(float key)
{
    float kcl = fminf(fmaxf(key, KMINF), KMAXF);
    int bin = (int)((KMAXF - kcl) * INVW);
    return min(NB-1, max(0, bin));
}

// ---------------------------------------------------------------------------
// k_pre: transform (vertex role) + face prep with inline transform + histogram
// ---------------------------------------------------------------------------
__global__ void k_pre(const float* __restrict__ verts,
                      const float* __restrict__ Km,
                      const float* __restrict__ Rt,
                      const int*   __restrict__ vi,
                      float* __restrict__ vpix)
{
    int t = blockIdx.x * blockDim.x + threadIdx.x;

    if (t < BB * VV) {                       // vertex role: write v_pix output
        int b = t / VV;
        float ox, oy, oz;
        xform(verts + t*3, Rt + b*12, Km + b*9, ox, oy, oz);
        vpix[t*3+0] = ox; vpix[t*3+1] = oy; vpix[t*3+2] = oz;
    }

    if (t < BB * FF) {                       // face role: prep + histogram
        int b = t / FF, f = t - b * FF;
        const float* R  = Rt + b*12;
        const float* Kk = Km + b*9;
        int i0 = vi[f*3+0], i1 = vi[f*3+1], i2 = vi[f*3+2];
        float ax, ay, az, bx, by, bz, cx, cy, cz;
        xform(verts + (b*VV + i0)*3, R, Kk, ax, ay, az);
        xform(verts + (b*VV + i1)*3, R, Kk, bx, by, bz);
        xform(verts + (b*VV + i2)*3, R, Kk, cx, cy, cz);

        float area = (bx-ax)*(cy-ay) - (by-ay)*(cx-ax);
        bool ok = (fabsf(area) > 1e-8f) && (az > 0.f) && (bz > 0.f) && (cz > 0.f);

        float key = -1.0f;
        unsigned bbits = 255u;               // lox=255, hix=0 -> always culled
        float4 F0 = make_float4(0,0,0,0), F1 = F0, F2 = F0, F3 = F0;
        float4 IZ = make_float4(0,0,0,0);
        if (ok) {
            float s  = (area > 0.f) ? 1.f : -1.f;
            float ia = 1.0f / area;
            float cc0 = ia / az, cc1 = ia / bz, cc2 = ia / cz;
            float sd0x = s*(cx-bx), sd0y = s*(cy-by);
            float sd1x = s*(ax-cx), sd1y = s*(ay-cy);
            float sd2x = s*(bx-ax), sd2y = s*(by-ay);
            float scc0 = s*cc0, scc1 = s*cc1, scc2 = s*cc2;
            float izdy = sd0x*scc0 + sd1x*scc1 + sd2x*scc2;
            F0 = make_float4(bx, by, sd0x, sd0y);
            F1 = make_float4(cx, cy, sd1x, sd1y);
            F2 = make_float4(ax, ay, sd2x, sd2y);
            F3 = make_float4(scc0, scc1, scc2, izdy);

            float mnx = fminf(ax, fminf(bx, cx)), mxx = fmaxf(ax, fmaxf(bx, cx));
            float mny = fminf(ay, fminf(by, cy)), mxy = fmaxf(ay, fmaxf(by, cy));
            float dd = (mxx - mnx) + (mxy - mny);
            float noise = 2.5e-7f * dd * dd * (fabsf(scc0)+fabsf(scc1)+fabsf(scc2));
            noise = fminf(noise, 10.f);
            key = fmaxf(1.0f/az, fmaxf(1.0f/bz, 1.0f/cz)) * 1.0001f + 1e-4f + noise;

            int lox = min(max((int)floorf((mnx - 0.5f) * 0.0625f),  0), 15);
            int hix = min(max((int)floorf((mxx - 0.5f) * 0.0625f), -1), 15) + 1;
            int loy = min(max((int)floorf((mny - 0.5f) * 0.0625f),  0), 15);
            int hiy = min(max((int)floorf((mxy - 0.5f) * 0.0625f), -1), 15) + 1;
            bbits = (unsigned)lox | ((unsigned)hix << 8)
                  | ((unsigned)loy << 16) | ((unsigned)hiy << 24);

            // affine invz bound: iz(p) = A*px + B*py + C  (CULL ONLY, padded)
            float A = -(sd0y*scc0 + sd1y*scc1 + sd2y*scc2);
            float Bc = izdy;
            float C = (sd0y*bx - sd0x*by)*scc0
                    + (sd1y*cx - sd1x*cy)*scc1
                    + (sd2y*ax - sd2x*ay)*scc2;
            float pad = noise + 1.2e-6f*((fabsf(A) + fabsf(Bc))*300.f + fabsf(C))
                      + 1e-7f;
            IZ = make_float4(A, Bc, C, fminf(pad, 10.f));
        }
        g_uF0[t] = F0; g_uF1[t] = F1; g_uF2[t] = F2; g_uF3[t] = F3;
        g_uBK[t] = make_float2(key, __uint_as_float(bbits));
        g_uIZ[t] = IZ;
        atomicAdd(&g_hist[b*NB + fixed_bin(key)], 1);
    }
}

// ---------------------------------------------------------------------------
// scatter (full records, coalesced sorted output) + per-block inline scan
// ---------------------------------------------------------------------------
__global__ __launch_bounds__(256) void k_scatter()
{
    __shared__ int s_base[BB*NB];
    __shared__ int s_warp[8];
    int tid = threadIdx.x, lane = tid & 31, wid = tid >> 5;

    for (int bb = 0; bb < BB; bb++) {
        int v[4], tsum = 0;
        int bi = bb*NB + tid*4;
#pragma unroll
        for (int k = 0; k < 4; k++) { v[k] = g_hist[bi+k]; tsum += v[k]; }
        int inc = tsum;
#pragma unroll
        for (int o = 1; o < 32; o <<= 1) {
            int y = __shfl_up_sync(0xffffffffu, inc, o);
            if (lane >= o) inc += y;
        }
        if (lane == 31) s_warp[wid] = inc;
        __syncthreads();
        if (wid == 0) {
            int s = (lane < 8) ? s_warp[lane] : 0;
#pragma unroll
            for (int o = 1; o < 8; o <<= 1) {
                int y = __shfl_up_sync(0xffffffffu, s, o);
                if (lane >= o) s += y;
            }
            if (lane < 8) s_warp[lane] = s;
        }
        __syncthreads();
        int pre = ((wid > 0) ? s_warp[wid-1] : 0) + inc - tsum;
#pragma unroll
        for (int k = 0; k < 4; k++) { s_base[bi+k] = pre; pre += v[k]; }
        __syncthreads();
    }

    int t = blockIdx.x * blockDim.x + tid;
    if (t < BB * FF) {
        int b = t / FF, f = t - b * FF;
        float2 bk = g_uBK[t];
        int bin = fixed_bin(bk.x);
        int pos = b*FF + s_base[b*NB + bin] + atomicAdd(&g_cur[b*NB + bin], 1);
        g_sF0[pos] = g_uF0[t];
        g_sF1[pos] = g_uF1[t];
        g_sF2[pos] = g_uF2[t];
        g_sF3[pos] = g_uF3[t];
        g_sBK[pos] = bk;
        g_sIZ[pos] = g_uIZ[t];
        g_sFid[pos] = f;
    }
}

// ---------------------------------------------------------------------------
// shading for one pixel (reference render+interpolate+grid_sample semantics)
// ---------------------------------------------------------------------------
__device__ __forceinline__ void shade_pixel(
    int b, int x, int y, int idx,
    const float* __restrict__ tex, const float* __restrict__ vt,
    const int* __restrict__ vi, const int* __restrict__ vti,
    const float* __restrict__ vpix, float* __restrict__ out)
{
    bool m  = (idx != -1);
    int it  = idx > 0 ? idx : 0;

    int i0 = vi[it*3+0], i1 = vi[it*3+1], i2 = vi[it*3+2];
    const float* pa = vpix + (b*VV + i0) * 3;
    const float* pb = vpix + (b*VV + i1) * 3;
    const float* pc = vpix + (b*VV + i2) * 3;
    float ax = pa[0], ay = pa[1], az = pa[2];
    float bx = pb[0], by = pb[1], bz = pb[2];
    float cx = pc[0], cy = pc[1], cz = pc[2];

    float px = x + 0.5f, py = y + 0.5f;
    float w0 = (cx-bx)*(py-by) - (cy-by)*(px-bx);
    float w1 = (ax-cx)*(py-cy) - (ay-cy)*(px-cx);
    float w2 = (bx-ax)*(py-ay) - (by-ay)*(px-ax);
    float area = w0 + w1 + w2;
    float ar = (fabsf(area) > 1e-8f) ? area : 1.0f;
    float f0 = w0 / ar / fmaxf(az, 1e-8f);
    float f1 = w1 / ar / fmaxf(bz, 1e-8f);
    float f2 = w2 / ar / fmaxf(cz, 1e-8f);
    float invz = f0 + f1 + f2;
    float invz_s = (fabsf(invz) > 1e-12f) ? invz : 1.0f;
    float depth = 1.0f / invz_s;
    float b0 = f0 / invz_s, b1 = f1 / invz_s, b2 = f2 / invz_s;

    float depth_o = m ? depth : 0.f;
    float bb0 = m ? b0 : 0.f;
    float bb1 = m ? b1 : 0.f;
    float bb2 = m ? b2 : 0.f;

    int t0 = vti[it*3+0], t1 = vti[it*3+1], t2 = vti[it*3+2];
    float a0x = vt[t0*2+0]*2.f - 1.f, a0y = vt[t0*2+1]*2.f - 1.f;
    float a1x = vt[t1*2+0]*2.f - 1.f, a1y = vt[t1*2+1]*2.f - 1.f;
    float a2x = vt[t2*2+0]*2.f - 1.f, a2y = vt[t2*2+1]*2.f - 1.f;
    float gxc = a0x*bb0 + a1x*bb1 + a2x*bb2;
    float gyc = a0y*bb0 + a1y*bb1 + a2y*bb2;

    float img0 = 0.f, img1 = 0.f, img2 = 0.f;
    if (m) {
        float sx = (gxc + 1.f) * (TW * 0.5f) - 0.5f;
        float sy = (gyc + 1.f) * (TW * 0.5f) - 0.5f;
        float fx0 = floorf(sx), fy0 = floorf(sy);
        float wx = sx - fx0, wy = sy - fy0;
        int x0 = (int)fx0, y0i = (int)fy0;
        float wgt[4] = { (1.f-wx)*(1.f-wy), wx*(1.f-wy), (1.f-wx)*wy, wx*wy };
        int cxs[4] = { x0, x0+1, x0,   x0+1 };
        int cys[4] = { y0i, y0i, y0i+1, y0i+1 };
        const float* tb = tex + (size_t)b * 3 * TW * TW;
#pragma unroll
        for (int c = 0; c < 4; c++) {
            int ix = cxs[c], iy = cys[c];
            bool val = (ix >= 0) && (ix < TW) && (iy >= 0) && (iy < TW);
            int ixc = min(max(ix, 0), TW-1);
            int iyc = min(max(iy, 0), TW-1);
            float wv = val ? wgt[c] : 0.f;
            size_t o = (size_t)iyc * TW + ixc;
            img0 += tb[0*TW*TW + o] * wv;
            img1 += tb[1*TW*TW + o] * wv;
            img2 += tb[2*TW*TW + o] * wv;
        }
    }

    int p = (b * HH + y) * WW + x;
    out[OFF_IMG   + ((b*3 + 0)*HH + y)*WW + x] = img0;
    out[OFF_IMG   + ((b*3 + 1)*HH + y)*WW + x] = img1;
    out[OFF_IMG   + ((b*3 + 2)*HH + y)*WW + x] = img2;
    out[OFF_DEPTH + p] = depth_o;
    out[OFF_VTIMG + ((b*2 + 0)*HH + y)*WW + x] = gxc;
    out[OFF_VTIMG + ((b*2 + 1)*HH + y)*WW + x] = gyc;
    out[OFF_INDEX + p] = (float)idx;
    out[OFF_BARY  + ((b*3 + 0)*HH + y)*WW + x] = bb0;
    out[OFF_BARY  + ((b*3 + 1)*HH + y)*WW + x] = bb1;
    out[OFF_BARY  + ((b*3 + 2)*HH + y)*WW + x] = bb2;
    out[OFF_MASK  + p] = m ? 1.f : 0.f;
}

// ---------------------------------------------------------------------------
// tile rasterizer: 16x16 tile, 128 thr, 2 px/thread. SINGLE sync per chunk:
// double-buffered {face slots, counts, s_min}; tileMin is the fresh block-min
// published LAST chunk (stale by one inner-iter -> strictly conservative).
// Selection math verbatim R5/R8 (bit-proven).
// ---------------------------------------------------------------------------
#define TPB    128
#define TILE   16

__global__ __launch_bounds__(TPB) void k_raster(
    const float* __restrict__ tex, const float* __restrict__ vt,
    const int* __restrict__ vi, const int* __restrict__ vti,
    const float* __restrict__ vpix, float* __restrict__ out)
{
    __shared__ float4 sF0[2][TPB], sF1[2][TPB], sF2[2][TPB], sF3[2][TPB];
    __shared__ int    sFid[2][TPB];
    __shared__ int    s_cnt[2][TPB/32];
    __shared__ float  s_min[2][TPB/32];

    int b   = blockIdx.z;
    int tx  = blockIdx.x, ty = blockIdx.y;
    int tx0 = tx * TILE, ty0 = ty * TILE;
    int tid = threadIdx.x;
    int warp = tid >> 5, lane = tid & 31;
    int lx  = tid & (TILE-1);
    int lyg = tid >> 4;                       // 0..7

    float px  = tx0 + lx + 0.5f;
    float py0 = ty0 + lyg * 2 + 0.5f;
    float txA = tx0 + 0.5f, txB = tx0 + TILE - 0.5f;
    float tyA = ty0 + 0.5f, tyB = ty0 + TILE - 0.5f;

    float biv0 = 0.f, biv1 = 0.f;
    int   bf0 = -1, bf1 = -1;

    if (tid < TPB/32) { s_min[0][tid] = 0.f; s_min[1][tid] = 0.f; }
    __syncthreads();

    const float4* f0A = g_sF0 + (size_t)b * FF;
    const float4* f1A = g_sF1 + (size_t)b * FF;
    const float4* f2A = g_sF2 + (size_t)b * FF;
    const float4* f3A = g_sF3 + (size_t)b * FF;
    const float2* bkA = g_sBK + (size_t)b * FF;
    const float4* izA = g_sIZ + (size_t)b * FF;
    const int*    fArr= g_sFid+ (size_t)b * FF;

    int p = 0;
    for (int base = 0; base < FF; base += TPB, p ^= 1) {
        // tileMin published at end of previous chunk (ordered by that sync);
        // stale by one inner-iteration -> smaller -> strictly conservative.
        float tileMin = fminf(fminf(s_min[p][0], s_min[p][1]),
                              fminf(s_min[p][2], s_min[p][3]));

        // sorted-stream break: all keys from base on <= binTop(bin(key[base]))
        float kb = bkA[base].x;
        int   bbin = fixed_bin(kb);
        if (bbin != 0) {
            float bound = KMAXF - (float)bbin * BWBIN + 1e-5f;
            if (bound <= tileMin) break;   // provably nothing left can win
        }

        // load + cull (depth-useless, tile-bbox miss, affine invz bound)
        int f = base + tid;
        float key = -1.0f; unsigned bbits = 255u;
        if (f < FF) {
            float2 bk = bkA[f];
            key = bk.x; bbits = __float_as_uint(bk.y);
        }
        bool keep = (key > tileMin);
        if (keep) {
            int lox = bbits & 255, hix = (bbits >> 8) & 255;
            int loy = (bbits >> 16) & 255, hiy = bbits >> 24;
            keep = (tx >= lox) && (tx < hix) && (ty >= loy) && (ty < hiy);
        }
        if (keep) {
            float4 iz = izA[f];
            float tmax = fmaxf(iz.x*txA, iz.x*txB)
                       + fmaxf(iz.y*tyA, iz.y*tyB) + iz.z + iz.w;
            keep = tmax > tileMin;
        }

        // warp-segmented compaction into buffer p
        unsigned bal = __ballot_sync(0xffffffffu, keep);
        if (lane == 0) s_cnt[p][warp] = __popc(bal);
        if (keep) {
            int pos = warp*32 + __popc(bal & ((1u << lane) - 1u));
            sF0[p][pos] = f0A[f]; sF1[p][pos] = f1A[f];
            sF2[p][pos] = f2A[f]; sF3[p][pos] = f3A[f];
            sFid[p][pos] = fArr[f];
        }

        // publish next chunk's tileMin into buffer p^1 (read after the sync
        // of THIS chunk by the next iteration)
        float wmin = fminf(biv0, biv1);
#pragma unroll
        for (int o = 16; o; o >>= 1)
            wmin = fminf(wmin, __shfl_xor_sync(0xffffffffu, wmin, o));
        if (lane == 0) s_min[p^1][warp] = wmin;

        __syncthreads();                       // the ONLY sync per chunk

        // inner loop over buffer p's warp segments
#pragma unroll
        for (int w = 0; w < TPB/32; w++) {
            int cw = s_cnt[p][w];
            for (int j = 0; j < cw; j++) {
                int idx = w*32 + j;
                float4 q0 = sF0[p][idx], q1 = sF1[p][idx];
                float4 q2 = sF2[p][idx], q3 = sF3[p][idx];
                float W0 = q0.z * (py0 - q0.y) - q0.w * (px - q0.x);
                float W1 = q1.z * (py0 - q1.y) - q1.w * (px - q1.x);
                float W2 = q2.z * (py0 - q2.y) - q2.w * (px - q2.x);
                float iz = W0 * q3.x + W1 * q3.y + W2 * q3.z;
                float tm = fminf(W0, fminf(W1, W2));
                if (tm >= 0.f && iz > biv0) { biv0 = iz; bf0 = sFid[p][idx]; }
                float W0b = W0 + q0.z, W1b = W1 + q1.z, W2b = W2 + q2.z;
                float izb = iz + q3.w;
                float tmb = fminf(W0b, fminf(W1b, W2b));
                if (tmb >= 0.f && izb > biv1) { biv1 = izb; bf1 = sFid[p][idx]; }
            }
        }
    }

    // re-zero sort state for the next graph replay (first call: zero-init globals)
    {
        int gb = (blockIdx.z * gridDim.y + blockIdx.y) * gridDim.x + blockIdx.x;
        int gt = gb * TPB + tid;
        if (gt < BB*NB) { g_hist[gt] = 0; g_cur[gt] = 0; }
    }

    // fused shading of this thread's 2 pixels
    int y0 = ty0 + lyg * 2;
    int x  = tx0 + lx;
    shade_pixel(b, x, y0,     bf0, tex, vt, vi, vti, vpix, out);
    shade_pixel(b, x, y0 + 1, bf1, tex, vt, vi, vti, vpix, out);
}

// ---------------------------------------------------------------------------
extern "C" void kernel_launch(void* const* d_in, const int* in_sizes, int n_in,
                              void* d_out, int out_size)
{
    const float* verts = (const float*)d_in[0];
    const float* tex   = (const float*)d_in[1];
    const float* Km    = (const float*)d_in[2];
    const float* Rt    = (const float*)d_in[3];
    const float* vt    = (const float*)d_in[4];
    const int*   vi    = (const int*)  d_in[5];
    const int*   vti   = (const int*)  d_in[6];
    float* out = (float*)d_out;

    float* vpix = out + OFF_VPIX;   // v_pix output doubles as scratch

    k_pre    <<<(BB*FF + 255)/256, 256>>>(verts, Km, Rt, vi, vpix);
    k_scatter<<<(BB*FF + 255)/256, 256>>>();
    dim3 rg(WW / TILE, HH / TILE, BB);
    k_raster <<<rg, TPB>>>(tex, vt, vi, vti, vpix, out);
}